// round 2
// baseline (speedup 1.0000x reference)
#include <cuda_runtime.h>
#include <math.h>

// Problem dims
#define Bn 8
#define Tn 96
#define Sn 192
#define Dn 512
#define BT (Bn*Tn)   // 768

// Scratch (device globals: no allocation allowed)
__device__ float g_wq[BT * Dn];        // [B,T,D]   inputs @ Wq^T
__device__ float g_uh[Bn * Sn * Dn];   // [B,S,D]   mems @ Wc^T + bc
__device__ float g_p [BT * Sn];        // [B,T,S]   raw scores, then softmax probs (in-place)
__device__ float g_c [BT * Dn];        // [B,T,D]   context

__device__ __forceinline__ float tanh_fast(float x) {
    float y;
    asm("tanh.approx.f32 %0, %1;" : "=f"(y) : "f"(x));
    return y;
}

// ----------------------------------------------------------------------------
// Fused GEMM 1+2: 64x64 tile, 256 threads, 4x4 microtile, NT (C = A @ W^T).
// blockIdx.y < 12  -> wq = inputs @ Wq^T           (rows 0..767)
// blockIdx.y >= 12 -> uh = mems @ Wc^T + bc        (rows 0..1535)
// K = 512 for both.
// ----------------------------------------------------------------------------
__global__ void __launch_bounds__(256) gemm12_fused(
    const float* __restrict__ inputs, const float* __restrict__ mems,
    const float* __restrict__ Wq, const float* __restrict__ Wc,
    const float* __restrict__ bc,
    float* __restrict__ wq_out, float* __restrict__ uh_out)
{
    const float* A; const float* W; const float* bias; float* C; int row0;
    if (blockIdx.y < 12) { A = inputs; W = Wq; bias = nullptr; C = wq_out; row0 = blockIdx.y * 64; }
    else                 { A = mems;   W = Wc; bias = bc;      C = uh_out; row0 = (blockIdx.y - 12) * 64; }

    __shared__ __align__(16) float As[16][68];
    __shared__ __align__(16) float Ws[16][68];

    const int tid  = threadIdx.x;
    const int tm   = tid >> 4;
    const int tn   = tid & 15;
    const int col0 = blockIdx.x * 64;
    const int lrow = tid >> 2;
    const int lk4  = (tid & 3) << 2;

    float acc[4][4] = {};

    for (int k0 = 0; k0 < Dn; k0 += 16) {
        float4 av = *(const float4*)(A + (size_t)(row0 + lrow) * Dn + k0 + lk4);
        float4 wv = *(const float4*)(W + (size_t)(col0 + lrow) * Dn + k0 + lk4);
        As[lk4 + 0][lrow] = av.x; As[lk4 + 1][lrow] = av.y;
        As[lk4 + 2][lrow] = av.z; As[lk4 + 3][lrow] = av.w;
        Ws[lk4 + 0][lrow] = wv.x; Ws[lk4 + 1][lrow] = wv.y;
        Ws[lk4 + 2][lrow] = wv.z; Ws[lk4 + 3][lrow] = wv.w;
        __syncthreads();

        #pragma unroll
        for (int k = 0; k < 16; k++) {
            float4 a = *(const float4*)&As[k][tm * 4];
            float4 b = *(const float4*)&Ws[k][tn * 4];
            float aa[4] = {a.x, a.y, a.z, a.w};
            float bb[4] = {b.x, b.y, b.z, b.w};
            #pragma unroll
            for (int i = 0; i < 4; i++)
                #pragma unroll
                for (int j = 0; j < 4; j++)
                    acc[i][j] += aa[i] * bb[j];
        }
        __syncthreads();
    }

    #pragma unroll
    for (int i = 0; i < 4; i++) {
        const int r = row0 + tm * 4 + i;
        const int c = col0 + tn * 4;
        float b0 = 0.f, b1 = 0.f, b2 = 0.f, b3 = 0.f;
        if (bias) { b0 = bias[c]; b1 = bias[c + 1]; b2 = bias[c + 2]; b3 = bias[c + 3]; }
        float4 o;
        o.x = acc[i][0] + b0; o.y = acc[i][1] + b1;
        o.z = acc[i][2] + b2; o.w = acc[i][3] + b3;
        *(float4*)(C + (size_t)r * Dn + c) = o;
    }
}

// ----------------------------------------------------------------------------
// GEMM3: C[M,N] = [A1|A2] @ W^T + bias. 32x64 tile, 128 threads, 4x4 microtile.
// K1 = K2 = 512, N = 512, M = 768 -> grid (8, 24) = 192 CTAs.
// ----------------------------------------------------------------------------
__global__ void __launch_bounds__(128) gemm3_dual(
    const float* __restrict__ A1, const float* __restrict__ A2,
    const float* __restrict__ W, const float* __restrict__ bias,
    float* __restrict__ C)
{
    const int K = 2 * Dn;
    __shared__ __align__(16) float As[16][36];
    __shared__ __align__(16) float Ws[16][68];

    const int tid  = threadIdx.x;
    const int tm   = tid >> 4;          // 0..7  -> rows tm*4..tm*4+3
    const int tn   = tid & 15;          // 0..15 -> cols tn*4..tn*4+3
    const int row0 = blockIdx.y * 32;
    const int col0 = blockIdx.x * 64;
    const int lr   = tid >> 2;          // 0..31
    const int lk4  = (tid & 3) << 2;    // 0,4,8,12

    float acc[4][4] = {};

    for (int k0 = 0; k0 < K; k0 += 16) {
        const int kk = k0 + lk4;
        float4 av;
        if (kk < Dn) av = *(const float4*)(A1 + (size_t)(row0 + lr) * Dn + kk);
        else         av = *(const float4*)(A2 + (size_t)(row0 + lr) * Dn + (kk - Dn));
        float4 w0 = *(const float4*)(W + (size_t)(col0 + lr)      * K + kk);
        float4 w1 = *(const float4*)(W + (size_t)(col0 + lr + 32) * K + kk);

        As[lk4 + 0][lr] = av.x; As[lk4 + 1][lr] = av.y;
        As[lk4 + 2][lr] = av.z; As[lk4 + 3][lr] = av.w;
        Ws[lk4 + 0][lr] = w0.x; Ws[lk4 + 1][lr] = w0.y;
        Ws[lk4 + 2][lr] = w0.z; Ws[lk4 + 3][lr] = w0.w;
        Ws[lk4 + 0][lr + 32] = w1.x; Ws[lk4 + 1][lr + 32] = w1.y;
        Ws[lk4 + 2][lr + 32] = w1.z; Ws[lk4 + 3][lr + 32] = w1.w;
        __syncthreads();

        #pragma unroll
        for (int k = 0; k < 16; k++) {
            float4 a = *(const float4*)&As[k][tm * 4];
            float4 b = *(const float4*)&Ws[k][tn * 4];
            float aa[4] = {a.x, a.y, a.z, a.w};
            float bb[4] = {b.x, b.y, b.z, b.w};
            #pragma unroll
            for (int i = 0; i < 4; i++)
                #pragma unroll
                for (int j = 0; j < 4; j++)
                    acc[i][j] += aa[i] * bb[j];
        }
        __syncthreads();
    }

    #pragma unroll
    for (int i = 0; i < 4; i++) {
        const int r = row0 + tm * 4 + i;
        const int c = col0 + tn * 4;
        float4 o;
        o.x = acc[i][0] + bias[c];     o.y = acc[i][1] + bias[c + 1];
        o.z = acc[i][2] + bias[c + 2]; o.w = acc[i][3] + bias[c + 3];
        *(float4*)(C + (size_t)r * Dn + c) = o;
    }
}

// ----------------------------------------------------------------------------
// Score kernel: raw[b,t,s] = sum_m tanh(wq[b,t,m] + uh[b,s,m]) * v[m].
// CTA = (s-half 96, t-tile 8, b). 256 threads = 8 warps, warp w -> t = t0+w,
// lane handles s = s0 + lane + {0,32,64}. uh staged in shared per 32-m chunk.
// ----------------------------------------------------------------------------
#define TT 8
__global__ void __launch_bounds__(256) score_kernel(
    const float* __restrict__ wq, const float* __restrict__ uh,
    const float* __restrict__ v, float* __restrict__ S_out)
{
    const int sh = blockIdx.x;          // 0/1 s-half
    const int t0 = blockIdx.y * TT;
    const int b  = blockIdx.z;
    const int tid = threadIdx.x, w = tid >> 5, lane = tid & 31;

    __shared__ __align__(16) float wq_sh[TT][Dn];
    __shared__ __align__(16) float v_sh[Dn];
    __shared__ __align__(16) float uh_sh[96][36];

    // load wq tile (8x512) + v (512)
    #pragma unroll
    for (int i = tid; i < TT * (Dn / 4); i += 256) {
        int t = i >> 7, j = i & 127;
        ((float4*)wq_sh[t])[j] =
            ((const float4*)(wq + ((size_t)(b * Tn + t0 + t)) * Dn))[j];
    }
    for (int i = tid; i < Dn / 4; i += 256)
        ((float4*)v_sh)[i] = ((const float4*)v)[i];

    const int s_base = sh * 96;
    float acc0 = 0.f, acc1 = 0.f, acc2 = 0.f;

    for (int m0 = 0; m0 < Dn; m0 += 32) {
        __syncthreads();
        // load uh chunk: 96 rows x 32 floats = 768 float4, 3 per thread
        #pragma unroll
        for (int i = tid; i < 768; i += 256) {
            int row = i >> 3, mm = (i & 7) << 2;
            *(float4*)&uh_sh[row][mm] =
                *(const float4*)(uh + ((size_t)(b * Sn + s_base + row)) * Dn + m0 + mm);
        }
        __syncthreads();

        #pragma unroll
        for (int mm = 0; mm < 32; mm += 4) {
            float4 wv = *(const float4*)&wq_sh[w][m0 + mm];
            float4 vv = *(const float4*)&v_sh[m0 + mm];
            float4 u0 = *(const float4*)&uh_sh[lane][mm];
            float4 u1 = *(const float4*)&uh_sh[lane + 32][mm];
            float4 u2 = *(const float4*)&uh_sh[lane + 64][mm];
            acc0 += tanh_fast(wv.x + u0.x) * vv.x;
            acc0 += tanh_fast(wv.y + u0.y) * vv.y;
            acc0 += tanh_fast(wv.z + u0.z) * vv.z;
            acc0 += tanh_fast(wv.w + u0.w) * vv.w;
            acc1 += tanh_fast(wv.x + u1.x) * vv.x;
            acc1 += tanh_fast(wv.y + u1.y) * vv.y;
            acc1 += tanh_fast(wv.z + u1.z) * vv.z;
            acc1 += tanh_fast(wv.w + u1.w) * vv.w;
            acc2 += tanh_fast(wv.x + u2.x) * vv.x;
            acc2 += tanh_fast(wv.y + u2.y) * vv.y;
            acc2 += tanh_fast(wv.z + u2.z) * vv.z;
            acc2 += tanh_fast(wv.w + u2.w) * vv.w;
        }
    }

    const size_t base = ((size_t)(b * Tn + t0 + w)) * Sn + s_base + lane;
    S_out[base]      = acc0;
    S_out[base + 32] = acc1;
    S_out[base + 64] = acc2;
}

// ----------------------------------------------------------------------------
// Softmax over s=192 with length mask. One warp per (b,t) row, in-place on S.
// ----------------------------------------------------------------------------
__global__ void __launch_bounds__(256) softmax_kernel(
    float* __restrict__ S, const int* __restrict__ lens,
    float* __restrict__ out_align, int write_align)
{
    const int wid  = blockIdx.x * 8 + (threadIdx.x >> 5);   // 0..767
    const int lane = threadIdx.x & 31;
    const int b = wid / Tn;
    float* row = S + (size_t)wid * Sn;
    const int L = lens[b];

    float vals[6];
    float mx = -INFINITY;
    #pragma unroll
    for (int k = 0; k < 6; k++) {
        int s = lane + 32 * k;
        float x = row[s];
        x = (s < L) ? x : -INFINITY;
        vals[k] = x;
        mx = fmaxf(mx, x);
    }
    #pragma unroll
    for (int o = 16; o; o >>= 1) mx = fmaxf(mx, __shfl_xor_sync(0xFFFFFFFFu, mx, o));

    float sum = 0.f;
    #pragma unroll
    for (int k = 0; k < 6; k++) {
        float e = (vals[k] == -INFINITY) ? 0.f : __expf(vals[k] - mx);
        vals[k] = e;
        sum += e;
    }
    #pragma unroll
    for (int o = 16; o; o >>= 1) sum += __shfl_xor_sync(0xFFFFFFFFu, sum, o);
    const float inv = __fdividef(1.f, sum);

    float* arow = out_align + (size_t)wid * Sn;
    #pragma unroll
    for (int k = 0; k < 6; k++) {
        float p = vals[k] * inv;
        row[lane + 32 * k] = p;
        if (write_align) arow[lane + 32 * k] = p;
    }
}

// ----------------------------------------------------------------------------
// Context as batched GEMM-NN: per b, C[96,512] = P[96,192] @ mems[192,512].
// 32x64 tile, 128 threads, 4x4 microtile. Grid (8, 3, 8) = 192 CTAs.
// ----------------------------------------------------------------------------
__global__ void __launch_bounds__(128) gemm_ctx(
    const float* __restrict__ P, const float* __restrict__ mems,
    float* __restrict__ C)
{
    const int b  = blockIdx.z;
    const int m0 = blockIdx.y * 32;
    const int n0 = blockIdx.x * 64;
    const float* A  = P    + (size_t)b * Tn * Sn;   // [96,192]
    const float* Bm = mems + (size_t)b * Sn * Dn;   // [192,512]

    __shared__ __align__(16) float As[16][36];
    __shared__ __align__(16) float Bs[16][68];

    const int tid = threadIdx.x;
    const int tm = tid >> 4, tn = tid & 15;

    float acc[4][4] = {};

    for (int k0 = 0; k0 < Sn; k0 += 16) {
        int m = tid >> 2, k4 = (tid & 3) << 2;
        float4 a4 = *(const float4*)(A + (size_t)(m0 + m) * Sn + k0 + k4);
        As[k4 + 0][m] = a4.x; As[k4 + 1][m] = a4.y;
        As[k4 + 2][m] = a4.z; As[k4 + 3][m] = a4.w;

        int kk = tid >> 4, nn = (tid & 15) << 2;
        float4 b0 = *(const float4*)(Bm + (size_t)(k0 + kk)     * Dn + n0 + nn);
        float4 b1 = *(const float4*)(Bm + (size_t)(k0 + kk + 8) * Dn + n0 + nn);
        *(float4*)&Bs[kk][nn]     = b0;
        *(float4*)&Bs[kk + 8][nn] = b1;
        __syncthreads();

        #pragma unroll
        for (int k = 0; k < 16; k++) {
            float4 a  = *(const float4*)&As[k][tm * 4];
            float4 bv = *(const float4*)&Bs[k][tn * 4];
            float aa[4] = {a.x, a.y, a.z, a.w};
            float bb[4] = {bv.x, bv.y, bv.z, bv.w};
            #pragma unroll
            for (int i = 0; i < 4; i++)
                #pragma unroll
                for (int j = 0; j < 4; j++)
                    acc[i][j] += aa[i] * bb[j];
        }
        __syncthreads();
    }

    #pragma unroll
    for (int i = 0; i < 4; i++) {
        float4 o;
        o.x = acc[i][0]; o.y = acc[i][1]; o.z = acc[i][2]; o.w = acc[i][3];
        *(float4*)(C + (size_t)(b * Tn + m0 + tm * 4 + i) * Dn + n0 + tn * 4) = o;
    }
}

// ----------------------------------------------------------------------------
extern "C" void kernel_launch(void* const* d_in, const int* in_sizes, int n_in,
                              void* d_out, int out_size)
{
    const float* inputs = (const float*)d_in[0];
    const float* mems   = (const float*)d_in[1];
    const int*   lens   = (const int*)  d_in[2];
    const float* Wq     = (const float*)d_in[3];
    const float* Wc     = (const float*)d_in[4];
    const float* bc     = (const float*)d_in[5];
    const float* v      = (const float*)d_in[6];
    const float* Wout   = (const float*)d_in[7];
    const float* bout   = (const float*)d_in[8];
    float* out = (float*)d_out;

    float *wqb, *uhb, *pb, *cb;
    cudaGetSymbolAddress((void**)&wqb, g_wq);
    cudaGetSymbolAddress((void**)&uhb, g_uh);
    cudaGetSymbolAddress((void**)&pb,  g_p);
    cudaGetSymbolAddress((void**)&cb,  g_c);

    const int attn_elems  = BT * Dn;
    const int align_elems = BT * Sn;
    const int write_align = (out_size >= attn_elems + align_elems) ? 1 : 0;
    float* out_align = out + attn_elems;

    // 1) wq + uh in one launch (288 CTAs)
    gemm12_fused<<<dim3(Dn / 64, 36), 256>>>(inputs, mems, Wq, Wc, bc, wqb, uhb);

    // 2) raw scores (192 CTAs)
    score_kernel<<<dim3(2, Tn / TT, Bn), 256>>>(wqb, uhb, v, pb);

    // 3) masked softmax in-place + export align (96 CTAs)
    softmax_kernel<<<BT / 8, 256>>>(pb, lens, out_align, write_align);

    // 4) context batched GEMM (192 CTAs)
    gemm_ctx<<<dim3(Dn / 64, Tn / 32, Bn), 128>>>(pb, mems, cb);

    // 5) attn_h = [c | inputs] @ Wout^T + bout (192 CTAs)
    gemm3_dual<<<dim3(Dn / 64, BT / 32), 128>>>(cb, inputs, Wout, bout, out);
}

// round 3
// speedup vs baseline: 1.8228x; 1.8228x over previous
#include <cuda_runtime.h>
#include <math.h>

#define Bn 8
#define Tn 96
#define Sn 192
#define Dn 512
#define BT (Bn*Tn)   // 768
#define BS (Bn*Sn)   // 1536

// Scratch
__device__ float g_wq  [BT * Dn];   // inputs @ Wq^T
__device__ float g_uh  [BS * Dn];   // mems @ Wc^T + bc
__device__ float g_wm  [BS * Dn];   // mems @ Woc^T   (Woc = Wout[:, :512])
__device__ float g_base[BT * Dn];   // inputs @ Woi^T + bout (Woi = Wout[:, 512:])
__device__ float g_p   [BT * Sn];   // softmax probs

__device__ __forceinline__ float tanh_fast(float x) {
    float y;
    asm("tanh.approx.f32 %0, %1;" : "=f"(y) : "f"(x));
    return y;
}

// ----------------------------------------------------------------------------
// Stage 1: four independent NT GEMMs in one launch, 64x64 tile, 256 thr,
// 4x4 microtile, double-buffered smem (one sync per 16-k chunk). K=512 all.
//   y<12 : wq   = inputs @ Wq^T
//   y<36 : uh   = mems @ Wc^T + bc
//   y<60 : Wm   = mems @ Woc^T          (Wout row n, cols 0..511, ld 1024)
//   else : base = inputs @ Woi^T + bout (Wout row n, cols 512..1023)
// ----------------------------------------------------------------------------
__global__ void __launch_bounds__(256) stage1_gemms(
    const float* __restrict__ inputs, const float* __restrict__ mems,
    const float* __restrict__ Wq, const float* __restrict__ Wc,
    const float* __restrict__ bc, const float* __restrict__ Wout,
    const float* __restrict__ bout,
    float* __restrict__ wq_o, float* __restrict__ uh_o,
    float* __restrict__ wm_o, float* __restrict__ base_o)
{
    const int y = blockIdx.y;
    const float* A; const float* W; int ldw; const float* bias; float* C; int row0;
    if (y < 12)      { A = inputs; W = Wq;         ldw = 512;  bias = nullptr; C = wq_o;   row0 = y * 64; }
    else if (y < 36) { A = mems;   W = Wc;         ldw = 512;  bias = bc;      C = uh_o;   row0 = (y-12)*64; }
    else if (y < 60) { A = mems;   W = Wout;       ldw = 1024; bias = nullptr; C = wm_o;   row0 = (y-36)*64; }
    else             { A = inputs; W = Wout + 512; ldw = 1024; bias = bout;    C = base_o; row0 = (y-60)*64; }

    __shared__ __align__(16) float As[2][16][68];
    __shared__ __align__(16) float Ws[2][16][68];

    const int tid  = threadIdx.x;
    const int tm   = tid >> 4;
    const int tn   = tid & 15;
    const int col0 = blockIdx.x * 64;
    const int lrow = tid >> 2;
    const int lk4  = (tid & 3) << 2;

    const float* aptr = A + (size_t)(row0 + lrow) * Dn + lk4;
    const float* wptr = W + (size_t)(col0 + lrow) * ldw + lk4;

    float acc[4][4] = {};

    float4 av = *(const float4*)aptr;
    float4 wv = *(const float4*)wptr;
    As[0][lk4+0][lrow] = av.x; As[0][lk4+1][lrow] = av.y;
    As[0][lk4+2][lrow] = av.z; As[0][lk4+3][lrow] = av.w;
    Ws[0][lk4+0][lrow] = wv.x; Ws[0][lk4+1][lrow] = wv.y;
    Ws[0][lk4+2][lrow] = wv.z; Ws[0][lk4+3][lrow] = wv.w;
    __syncthreads();

    #pragma unroll 1
    for (int c = 0; c < 32; c++) {
        const int cur = c & 1;
        if (c < 31) {
            av = *(const float4*)(aptr + (c + 1) * 16);
            wv = *(const float4*)(wptr + (c + 1) * 16);
        }
        #pragma unroll
        for (int k = 0; k < 16; k++) {
            float4 a = *(const float4*)&As[cur][k][tm * 4];
            float4 b = *(const float4*)&Ws[cur][k][tn * 4];
            float aa[4] = {a.x, a.y, a.z, a.w};
            float bb[4] = {b.x, b.y, b.z, b.w};
            #pragma unroll
            for (int i = 0; i < 4; i++)
                #pragma unroll
                for (int j = 0; j < 4; j++)
                    acc[i][j] += aa[i] * bb[j];
        }
        if (c < 31) {
            const int nxt = cur ^ 1;
            As[nxt][lk4+0][lrow] = av.x; As[nxt][lk4+1][lrow] = av.y;
            As[nxt][lk4+2][lrow] = av.z; As[nxt][lk4+3][lrow] = av.w;
            Ws[nxt][lk4+0][lrow] = wv.x; Ws[nxt][lk4+1][lrow] = wv.y;
            Ws[nxt][lk4+2][lrow] = wv.z; Ws[nxt][lk4+3][lrow] = wv.w;
            __syncthreads();
        }
    }

    #pragma unroll
    for (int i = 0; i < 4; i++) {
        const int r = row0 + tm * 4 + i;
        const int cc = col0 + tn * 4;
        float b0=0.f,b1=0.f,b2=0.f,b3=0.f;
        if (bias) { b0=bias[cc]; b1=bias[cc+1]; b2=bias[cc+2]; b3=bias[cc+3]; }
        float4 o;
        o.x = acc[i][0]+b0; o.y = acc[i][1]+b1; o.z = acc[i][2]+b2; o.w = acc[i][3]+b3;
        *(float4*)(C + (size_t)r * Dn + cc) = o;
    }
}

// ----------------------------------------------------------------------------
// Stage 2: fused score + masked softmax.
// CTA = (t-tile of 4, b), 128 threads = 4 warps; warp w -> t = t0+w,
// lane covers s = lane + 32*{0..5}. uh staged in smem per 32-m chunk.
// ----------------------------------------------------------------------------
__global__ void __launch_bounds__(128) score_softmax(
    const float* __restrict__ wq, const float* __restrict__ uh,
    const float* __restrict__ v, const int* __restrict__ lens,
    float* __restrict__ P, float* __restrict__ out_align, int write_align)
{
    const int t0 = blockIdx.x * 4;
    const int b  = blockIdx.y;
    const int tid = threadIdx.x, w = tid >> 5, lane = tid & 31;

    __shared__ __align__(16) float wq_sh[4][Dn];
    __shared__ __align__(16) float v_sh[Dn];
    __shared__ __align__(16) float uh_sh[Sn][36];

    for (int i = tid; i < 4 * (Dn/4); i += 128) {
        int t = i >> 7, j = i & 127;
        ((float4*)wq_sh[t])[j] = ((const float4*)(wq + ((size_t)(b*Tn + t0 + t)) * Dn))[j];
    }
    for (int i = tid; i < Dn/4; i += 128)
        ((float4*)v_sh)[i] = ((const float4*)v)[i];

    float a0=0.f,a1=0.f,a2=0.f,a3=0.f,a4=0.f,a5=0.f;

    for (int m0 = 0; m0 < Dn; m0 += 32) {
        __syncthreads();
        #pragma unroll
        for (int i = tid; i < Sn * 8; i += 128) {        // 1536 float4
            int row = i >> 3, mm = (i & 7) << 2;
            *(float4*)&uh_sh[row][mm] =
                *(const float4*)(uh + ((size_t)(b*Sn + row)) * Dn + m0 + mm);
        }
        __syncthreads();

        #pragma unroll
        for (int mm = 0; mm < 32; mm += 4) {
            float4 wv = *(const float4*)&wq_sh[w][m0 + mm];
            float4 vv = *(const float4*)&v_sh[m0 + mm];
            float4 u0 = *(const float4*)&uh_sh[lane      ][mm];
            float4 u1 = *(const float4*)&uh_sh[lane +  32][mm];
            float4 u2 = *(const float4*)&uh_sh[lane +  64][mm];
            float4 u3 = *(const float4*)&uh_sh[lane +  96][mm];
            float4 u4 = *(const float4*)&uh_sh[lane + 128][mm];
            float4 u5 = *(const float4*)&uh_sh[lane + 160][mm];
            a0 += tanh_fast(wv.x+u0.x)*vv.x; a0 += tanh_fast(wv.y+u0.y)*vv.y;
            a0 += tanh_fast(wv.z+u0.z)*vv.z; a0 += tanh_fast(wv.w+u0.w)*vv.w;
            a1 += tanh_fast(wv.x+u1.x)*vv.x; a1 += tanh_fast(wv.y+u1.y)*vv.y;
            a1 += tanh_fast(wv.z+u1.z)*vv.z; a1 += tanh_fast(wv.w+u1.w)*vv.w;
            a2 += tanh_fast(wv.x+u2.x)*vv.x; a2 += tanh_fast(wv.y+u2.y)*vv.y;
            a2 += tanh_fast(wv.z+u2.z)*vv.z; a2 += tanh_fast(wv.w+u2.w)*vv.w;
            a3 += tanh_fast(wv.x+u3.x)*vv.x; a3 += tanh_fast(wv.y+u3.y)*vv.y;
            a3 += tanh_fast(wv.z+u3.z)*vv.z; a3 += tanh_fast(wv.w+u3.w)*vv.w;
            a4 += tanh_fast(wv.x+u4.x)*vv.x; a4 += tanh_fast(wv.y+u4.y)*vv.y;
            a4 += tanh_fast(wv.z+u4.z)*vv.z; a4 += tanh_fast(wv.w+u4.w)*vv.w;
            a5 += tanh_fast(wv.x+u5.x)*vv.x; a5 += tanh_fast(wv.y+u5.y)*vv.y;
            a5 += tanh_fast(wv.z+u5.z)*vv.z; a5 += tanh_fast(wv.w+u5.w)*vv.w;
        }
    }

    // masked softmax over the 6 per-lane values (s = lane + 32k)
    const int L = lens[b];
    float vals[6] = {a0,a1,a2,a3,a4,a5};
    float mx = -INFINITY;
    #pragma unroll
    for (int k = 0; k < 6; k++) {
        if (lane + 32*k >= L) vals[k] = -INFINITY;
        mx = fmaxf(mx, vals[k]);
    }
    #pragma unroll
    for (int o = 16; o; o >>= 1) mx = fmaxf(mx, __shfl_xor_sync(0xFFFFFFFFu, mx, o));
    float sum = 0.f;
    #pragma unroll
    for (int k = 0; k < 6; k++) {
        float e = (vals[k] == -INFINITY) ? 0.f : __expf(vals[k] - mx);
        vals[k] = e; sum += e;
    }
    #pragma unroll
    for (int o = 16; o; o >>= 1) sum += __shfl_xor_sync(0xFFFFFFFFu, sum, o);
    const float inv = __fdividef(1.f, sum);

    const size_t rb = ((size_t)(b*Tn + t0 + w)) * Sn + lane;
    #pragma unroll
    for (int k = 0; k < 6; k++) {
        float p = vals[k] * inv;
        P[rb + 32*k] = p;
        if (write_align) out_align[rb + 32*k] = p;
    }
}

// ----------------------------------------------------------------------------
// Stage 3: out[b,t,:] = P[b] @ Wm[b] + base.  16x64 tile, 128 thr, 2x4 micro.
// Grid (8, 6, 8) = 384 CTAs.
// ----------------------------------------------------------------------------
__global__ void __launch_bounds__(128) stage3_epilogue(
    const float* __restrict__ P, const float* __restrict__ Wm,
    const float* __restrict__ base, float* __restrict__ out)
{
    const int b  = blockIdx.z;
    const int m0 = blockIdx.y * 16;
    const int n0 = blockIdx.x * 64;
    const float* A  = P  + (size_t)b * Tn * Sn;   // [96,192]
    const float* Bm = Wm + (size_t)b * Sn * Dn;   // [192,512]

    __shared__ __align__(16) float As[16][20];
    __shared__ __align__(16) float Bs[16][68];

    const int tid = threadIdx.x;
    const int tm = tid >> 4;    // 0..7 -> rows tm*2, tm*2+1
    const int tn = tid & 15;    // cols tn*4

    float acc[2][4] = {};

    for (int k0 = 0; k0 < Sn; k0 += 16) {
        if (tid < 64) {
            int m = tid >> 2, k4 = (tid & 3) << 2;
            float4 a4 = *(const float4*)(A + (size_t)(m0 + m) * Sn + k0 + k4);
            As[k4+0][m] = a4.x; As[k4+1][m] = a4.y;
            As[k4+2][m] = a4.z; As[k4+3][m] = a4.w;
        }
        {
            int kk = tid >> 4, nn = (tid & 15) << 2;
            float4 b0 = *(const float4*)(Bm + (size_t)(k0 + kk)     * Dn + n0 + nn);
            float4 b1 = *(const float4*)(Bm + (size_t)(k0 + kk + 8) * Dn + n0 + nn);
            *(float4*)&Bs[kk][nn]     = b0;
            *(float4*)&Bs[kk + 8][nn] = b1;
        }
        __syncthreads();

        #pragma unroll
        for (int k = 0; k < 16; k++) {
            float a0 = As[k][tm*2], a1 = As[k][tm*2+1];
            float4 bv = *(const float4*)&Bs[k][tn*4];
            acc[0][0] += a0*bv.x; acc[0][1] += a0*bv.y; acc[0][2] += a0*bv.z; acc[0][3] += a0*bv.w;
            acc[1][0] += a1*bv.x; acc[1][1] += a1*bv.y; acc[1][2] += a1*bv.z; acc[1][3] += a1*bv.w;
        }
        __syncthreads();
    }

    #pragma unroll
    for (int i = 0; i < 2; i++) {
        const size_t r = (size_t)(b*Tn + m0 + tm*2 + i) * Dn + n0 + tn*4;
        float4 bb = *(const float4*)(base + r);
        float4 o;
        o.x = acc[i][0]+bb.x; o.y = acc[i][1]+bb.y;
        o.z = acc[i][2]+bb.z; o.w = acc[i][3]+bb.w;
        *(float4*)(out + r) = o;
    }
}

// ----------------------------------------------------------------------------
extern "C" void kernel_launch(void* const* d_in, const int* in_sizes, int n_in,
                              void* d_out, int out_size)
{
    const float* inputs = (const float*)d_in[0];
    const float* mems   = (const float*)d_in[1];
    const int*   lens   = (const int*)  d_in[2];
    const float* Wq     = (const float*)d_in[3];
    const float* Wc     = (const float*)d_in[4];
    const float* bc     = (const float*)d_in[5];
    const float* v      = (const float*)d_in[6];
    const float* Wout   = (const float*)d_in[7];
    const float* bout   = (const float*)d_in[8];
    float* out = (float*)d_out;

    float *wqb, *uhb, *wmb, *baseb, *pb;
    cudaGetSymbolAddress((void**)&wqb,   g_wq);
    cudaGetSymbolAddress((void**)&uhb,   g_uh);
    cudaGetSymbolAddress((void**)&wmb,   g_wm);
    cudaGetSymbolAddress((void**)&baseb, g_base);
    cudaGetSymbolAddress((void**)&pb,    g_p);

    const int attn_elems  = BT * Dn;
    const int align_elems = BT * Sn;
    const int write_align = (out_size >= attn_elems + align_elems) ? 1 : 0;
    float* out_align = out + attn_elems;

    // 1) wq, uh, Wm, base — one launch, 576 CTAs
    stage1_gemms<<<dim3(Dn/64, 72), 256>>>(
        inputs, mems, Wq, Wc, bc, Wout, bout, wqb, uhb, wmb, baseb);

    // 2) score + masked softmax — 192 CTAs
    score_softmax<<<dim3(Tn/4, Bn), 128>>>(wqb, uhb, v, lens, pb, out_align, write_align);

    // 3) out = P @ Wm + base — 384 CTAs
    stage3_epilogue<<<dim3(Dn/64, Tn/16, Bn), 128>>>(pb, wmb, baseb, out);
}